// round 2
// baseline (speedup 1.0000x reference)
#include <cuda_runtime.h>

// ---------------------------------------------------------------------------
// SpatioTemporalGNNLayer: out = relu(conv3x3(x,Ww)+Wb + conv3x3(agg,Bw)+Bb)
// agg[dst] = mean over edges of x[src].
//
// CSR build (detect edge dtype -> count -> scan -> fill), then ONE fused
// per-node kernel: gather-mean into smem + both convs + relu.
// ---------------------------------------------------------------------------

#define NNODES 4096
#define NEDGES 16384
#define NODE_ELEMS 4096          // 16*16*16
#define CIN 16
#define COUT 16
#define ROWSTRIDE 20             // padded floats per image row in smem (80B)
#define CHSTRIDE (18*ROWSTRIDE)  // 1 zero row above + 16 + 1 below = 360 floats
#define NMASK (NNODES - 1)

__device__ int g_deg[NNODES];
__device__ int g_cur[NNODES];
__device__ int g_off[NNODES + 1];
__device__ int g_srcs[NEDGES];
__device__ int g_is64;

// ---------------------------------------------------------------------------
// Detect whether edge_index is int64 or int32. If int64 (little-endian),
// the high 32-bit word of every value (< 4096) is zero.
__global__ void detect_kernel(const int* __restrict__ ei32, int E) {
    if (threadIdx.x == 0 && blockIdx.x == 0) {
        int is64 = 1;
        int n = (E < 64) ? E : 64;
        for (int i = 0; i < n; i++)
            if (ei32[2 * i + 1] != 0) { is64 = 0; break; }
        g_is64 = is64;
    }
}

__global__ void zero_kernel() {
    int i = blockIdx.x * blockDim.x + threadIdx.x;
    if (i < NNODES) { g_deg[i] = 0; g_cur[i] = 0; }
}

__device__ __forceinline__ int load_idx(const int* ei32, int pos) {
    // pos is the logical element index into the flattened [2,E] array
    return g_is64 ? (ei32[2 * pos] & NMASK) : (ei32[pos] & NMASK);
}

__global__ void count_kernel(const int* __restrict__ ei32, int E) {
    int e = blockIdx.x * blockDim.x + threadIdx.x;
    if (e < E) {
        int d = load_idx(ei32, E + e);
        atomicAdd(&g_deg[d], 1);
    }
}

// exclusive scan over 4096 counters, one CTA of 1024 threads, 4 items/thread
__global__ void scan_kernel() {
    __shared__ int s[1024];
    int t = threadIdx.x;
    int v0 = g_deg[4 * t + 0];
    int v1 = g_deg[4 * t + 1];
    int v2 = g_deg[4 * t + 2];
    int v3 = g_deg[4 * t + 3];
    int sum = v0 + v1 + v2 + v3;
    s[t] = sum;
    __syncthreads();
    for (int d = 1; d < 1024; d <<= 1) {
        int val = (t >= d) ? s[t - d] : 0;
        __syncthreads();
        s[t] += val;
        __syncthreads();
    }
    int excl = s[t] - sum;
    g_off[4 * t + 0] = excl;
    g_off[4 * t + 1] = excl + v0;
    g_off[4 * t + 2] = excl + v0 + v1;
    g_off[4 * t + 3] = excl + v0 + v1 + v2;
    if (t == 1023) g_off[NNODES] = s[t];
}

__global__ void fill_kernel(const int* __restrict__ ei32, int E) {
    int e = blockIdx.x * blockDim.x + threadIdx.x;
    if (e < E) {
        int sc = load_idx(ei32, e);
        int d  = load_idx(ei32, E + e);
        int pos = g_off[d] + atomicAdd(&g_cur[d], 1);
        g_srcs[pos] = sc;
    }
}

// ---------------------------------------------------------------------------
__device__ __forceinline__ void load_row16(float* r, const float* p) {
    const float4* p4 = (const float4*)p;
#pragma unroll
    for (int k = 0; k < 4; k++) {
        float4 v = p4[k];
        r[4 * k + 0] = v.x; r[4 * k + 1] = v.y;
        r[4 * k + 2] = v.z; r[4 * k + 3] = v.w;
    }
}

// Accumulate one 3x3 conv channel contribution for 16 pixels of one row.
// ch points at a vertically zero-padded channel image (18 rows x ROWSTRIDE).
__device__ __forceinline__ void conv_accum(const float* __restrict__ ch, int row,
                                           const float* __restrict__ w, float* acc) {
    float rT[18], rM[18], rB[18];
    rT[0] = 0.f; rT[17] = 0.f;
    rM[0] = 0.f; rM[17] = 0.f;
    rB[0] = 0.f; rB[17] = 0.f;
    load_row16(rT + 1, ch + (row)     * ROWSTRIDE);
    load_row16(rM + 1, ch + (row + 1) * ROWSTRIDE);
    load_row16(rB + 1, ch + (row + 2) * ROWSTRIDE);
    float w0 = w[0], w1 = w[1], w2 = w[2];
    float w3 = w[3], w4 = w[4], w5 = w[5];
    float w6 = w[6], w7 = w[7], w8 = w[8];
#pragma unroll
    for (int px = 0; px < 16; px++) {
        float s = acc[px];
        s = fmaf(w0, rT[px],     s);
        s = fmaf(w1, rT[px + 1], s);
        s = fmaf(w2, rT[px + 2], s);
        s = fmaf(w3, rM[px],     s);
        s = fmaf(w4, rM[px + 1], s);
        s = fmaf(w5, rM[px + 2], s);
        s = fmaf(w6, rB[px],     s);
        s = fmaf(w7, rB[px + 1], s);
        s = fmaf(w8, rB[px + 2], s);
        acc[px] = s;
    }
}

__global__ __launch_bounds__(256, 2) void gnn_main_kernel(
    const float* __restrict__ x,
    const float* __restrict__ Ww, const float* __restrict__ Wbias,
    const float* __restrict__ Bw, const float* __restrict__ Bbias,
    float* __restrict__ out) {
    extern __shared__ float sm[];
    float* xs  = sm;                        // 16 * 360
    float* as  = xs + CIN * CHSTRIDE;       // 16 * 360
    float* sWw = as + CIN * CHSTRIDE;       // 2304
    float* sBw = sWw + 2304;                // 2304
    float* sWb = sBw + 2304;                // 16
    float* sBb = sWb + 16;                  // 16

    int tid  = threadIdx.x;
    int node = blockIdx.x;

    // stage weights
    for (int i = tid; i < 2304; i += 256) { sWw[i] = Ww[i]; sBw[i] = Bw[i]; }
    if (tid < 16) { sWb[tid] = Wbias[tid]; sBb[tid] = Bbias[tid]; }

    // zero the vertical pad rows (y=-1 and y=16, cols 0..15) of both buffers
    for (int i = tid; i < 512; i += 256) {
        int ci = i >> 5;
        int j  = i & 31;
        int off = ci * CHSTRIDE + ((j < 16) ? j : (17 * ROWSTRIDE + (j - 16)));
        xs[off] = 0.f;
        as[off] = 0.f;
    }

    // gather-mean over incoming edges (register accumulate, 4 float4/thread)
    const float4* xp = (const float4*)(x + (size_t)node * NODE_ELEMS);
    float4 a[4];
#pragma unroll
    for (int k = 0; k < 4; k++) a[k] = make_float4(0.f, 0.f, 0.f, 0.f);

    int beg = g_off[node], end = g_off[node + 1];
    for (int e = beg; e < end; e++) {
        int sc = g_srcs[e] & NMASK;
        const float4* sp = (const float4*)(x + (size_t)sc * NODE_ELEMS);
#pragma unroll
        for (int k = 0; k < 4; k++) {
            float4 v = __ldg(&sp[tid + 256 * k]);
            a[k].x += v.x; a[k].y += v.y; a[k].z += v.z; a[k].w += v.w;
        }
    }
    float inv = 1.0f / (float)max(end - beg, 1);

    // scatter x[node] and agg into padded smem layout
    float4* xs4 = (float4*)xs;
    float4* as4 = (float4*)as;
#pragma unroll
    for (int k = 0; k < 4; k++) {
        int i4  = tid + 256 * k;          // float4 index within node block
        int ci  = i4 >> 6;                // 64 float4 per channel
        int rem = i4 & 63;
        int y   = rem >> 2;               // 4 float4 per row
        int x4  = rem & 3;
        int d4  = ci * (CHSTRIDE / 4) + (y + 1) * (ROWSTRIDE / 4) + x4;
        xs4[d4] = xp[i4];
        as4[d4] = make_float4(a[k].x * inv, a[k].y * inv, a[k].z * inv, a[k].w * inv);
    }
    __syncthreads();

    // conv phase: thread (co,row) computes 16 output pixels
    int co  = tid >> 4;
    int row = tid & 15;
    float bias = sWb[co] + sBb[co];
    float acc[16];
#pragma unroll
    for (int j = 0; j < 16; j++) acc[j] = bias;

#pragma unroll 1
    for (int ci = 0; ci < 16; ci++) {
        conv_accum(xs + ci * CHSTRIDE, row, sWw + (co * 16 + ci) * 9, acc);
        conv_accum(as + ci * CHSTRIDE, row, sBw + (co * 16 + ci) * 9, acc);
    }

    float4* op4 = (float4*)(out + (size_t)node * NODE_ELEMS + co * 256 + row * 16);
#pragma unroll
    for (int k = 0; k < 4; k++) {
        op4[k] = make_float4(fmaxf(acc[4 * k + 0], 0.f), fmaxf(acc[4 * k + 1], 0.f),
                             fmaxf(acc[4 * k + 2], 0.f), fmaxf(acc[4 * k + 3], 0.f));
    }
}

// ---------------------------------------------------------------------------
extern "C" void kernel_launch(void* const* d_in, const int* in_sizes, int n_in,
                              void* d_out, int out_size) {
    const float* x   = (const float*)d_in[0];
    const int*   ei  = (const int*)d_in[1];   // int32 view; detect_kernel resolves dtype
    const float* Ww  = (const float*)d_in[2];
    const float* Wb  = (const float*)d_in[3];
    const float* Bw  = (const float*)d_in[4];
    const float* Bb  = (const float*)d_in[5];
    float*       out = (float*)d_out;

    int E = in_sizes[1] / 2;
    int N = in_sizes[0] / NODE_ELEMS;

    detect_kernel<<<1, 32>>>(ei, E);
    zero_kernel<<<(NNODES + 255) / 256, 256>>>();
    count_kernel<<<(E + 255) / 256, 256>>>(ei, E);
    scan_kernel<<<1, 1024>>>();
    fill_kernel<<<(E + 255) / 256, 256>>>(ei, E);

    int smem_bytes = (2 * CIN * CHSTRIDE + 2 * 2304 + 32) * (int)sizeof(float); // 64640
    cudaFuncSetAttribute(gnn_main_kernel,
                         cudaFuncAttributeMaxDynamicSharedMemorySize, smem_bytes);
    gnn_main_kernel<<<N, 256, smem_bytes>>>(x, Ww, Wb, Bw, Bb, out);
}